// round 4
// baseline (speedup 1.0000x reference)
#include <cuda_runtime.h>
#include <cstdint>

#define TT 33
#define CC 512
#define DK 64
#define NJ 192           // 3*DK
#define BPC 4            // batches per CTA
#define MR 132           // valid rows (BPC*TT)
#define MPAD 144         // padded M tile (9*16)
#define KC 32            // K chunk
#define PITCH 36         // smem row pitch (floats)
#define NT 384           // 12 warps: 3m x 4n
#define QP 200           // qkv smem pitch
#define SP 34            // score smem pitch

// floats: A bufs 2*144*36=10368 | B bufs 2*192*36=13824 | qkv 132*200=26400 | sc 132*34=4488
#define F_A0   0
#define F_A1   (MPAD * PITCH)
#define F_B0   (2 * MPAD * PITCH)
#define F_B1   (F_B0 + NJ * PITCH)
#define F_QKV  (F_B1 + NJ * PITCH)
#define F_SC   (F_QKV + MR * QP)
#define SMEM_FLOATS (F_SC + MR * SP)      // 55080 floats = 220320 B

__device__ float g_wt[NJ * CC];           // tf32-rounded W, [n][c]

__device__ __forceinline__ uint32_t f2tf32(float f) {
    uint32_t u;
    asm("cvt.rna.tf32.f32 %0, %1;" : "=r"(u) : "f"(f));
    return u;
}

__device__ __forceinline__ void mma_tf32(float* d, const uint32_t* a, const uint32_t* b) {
    asm volatile(
        "mma.sync.aligned.m16n8k8.row.col.f32.tf32.tf32.f32 "
        "{%0,%1,%2,%3}, {%4,%5,%6,%7}, {%8,%9}, {%0,%1,%2,%3};\n"
        : "+f"(d[0]), "+f"(d[1]), "+f"(d[2]), "+f"(d[3])
        : "r"(a[0]), "r"(a[1]), "r"(a[2]), "r"(a[3]), "r"(b[0]), "r"(b[1]));
}

__device__ __forceinline__ void cp_async16(void* smem_dst, const void* gsrc) {
    uint32_t s = (uint32_t)__cvta_generic_to_shared(smem_dst);
    asm volatile("cp.async.cg.shared.global [%0], [%1], 16;\n" :: "r"(s), "l"(gsrc));
}
#define CP_COMMIT() asm volatile("cp.async.commit_group;\n" ::: "memory")
#define CP_WAIT0()  asm volatile("cp.async.wait_group 0;\n" ::: "memory")

__global__ void prep_w(const float* __restrict__ Wq, const float* __restrict__ Wk,
                       const float* __restrict__ Wv) {
    int i = blockIdx.x * blockDim.x + threadIdx.x;
    if (i < NJ * CC) {
        int n = i / CC, c = i - n * CC;
        float v = (n < DK)     ? Wq[n * CC + c]
                : (n < 2 * DK) ? Wk[(n - DK) * CC + c]
                               : Wv[(n - 2 * DK) * CC + c];
        g_wt[i] = __uint_as_float(f2tf32(v));
    }
}

__global__ __launch_bounds__(NT, 1)
void head_fused(const float* __restrict__ x, float* __restrict__ out,
                int Btot, size_t Mtot) {
    extern __shared__ float sm[];
    float* Asb[2] = { sm + F_A0, sm + F_A1 };
    float* Bsb[2] = { sm + F_B0, sm + F_B1 };
    float* qkv    = sm + F_QKV;
    float* sc     = sm + F_SC;

    const int tid  = threadIdx.x;
    const int wid  = tid >> 5, lane = tid & 31;
    const int wn   = wid & 3;          // n offset 48*wn
    const int wm   = wid >> 2;         // m offset 48*wm (0..2)
    const int g    = lane >> 2;        // 0..7
    const int tg   = lane & 3;         // 0..3
    const int r0   = tid >> 3;         // 0..47 staging row
    const int q    = tid & 7;          // 0..7  staging float4 col
    const size_t mbase = (size_t)blockIdx.x * MR;

    float acc[3][6][4];
    #pragma unroll
    for (int i = 0; i < 3; ++i)
        #pragma unroll
        for (int j = 0; j < 6; ++j)
            #pragma unroll
            for (int e = 0; e < 4; ++e) acc[i][j][e] = 0.f;

    float4 areg[3];

    // ---- prologue: chunk 0
    #pragma unroll
    for (int j = 0; j < 4; ++j) {      // B chunk 0 -> buf 0 (192 rows)
        int n = r0 + 48 * j;
        cp_async16(&Bsb[0][n * PITCH + q * 4], g_wt + (size_t)n * CC + q * 4);
    }
    CP_COMMIT();
    #pragma unroll
    for (int i = 0; i < 3; ++i) {      // A chunk 0 -> regs (144 rows, pad zero)
        int r = r0 + 48 * i;
        size_t m = mbase + (size_t)r;
        areg[i] = (r < MR && m < Mtot) ? *(const float4*)(x + m * CC + q * 4)
                                       : make_float4(0.f, 0.f, 0.f, 0.f);
    }

    for (int kt = 0; kt < CC / KC; ++kt) {
        const int buf = kt & 1;
        __syncthreads();               // prev compute done; buffers reusable
        #pragma unroll
        for (int i = 0; i < 3; ++i) {  // STS A (tf32-rounded)
            float4 v;
            v.x = __uint_as_float(f2tf32(areg[i].x));
            v.y = __uint_as_float(f2tf32(areg[i].y));
            v.z = __uint_as_float(f2tf32(areg[i].z));
            v.w = __uint_as_float(f2tf32(areg[i].w));
            *(float4*)&Asb[buf][(r0 + 48 * i) * PITCH + q * 4] = v;
        }
        CP_WAIT0();
        __syncthreads();

        if (kt + 1 < CC / KC) {        // prefetch chunk kt+1
            const int nb = buf ^ 1;
            #pragma unroll
            for (int j = 0; j < 4; ++j) {
                int n = r0 + 48 * j;
                cp_async16(&Bsb[nb][n * PITCH + q * 4],
                           g_wt + (size_t)n * CC + (kt + 1) * KC + q * 4);
            }
            CP_COMMIT();
            #pragma unroll
            for (int i = 0; i < 3; ++i) {
                int r = r0 + 48 * i;
                size_t m = mbase + (size_t)r;
                areg[i] = (r < MR && m < Mtot)
                        ? *(const float4*)(x + m * CC + (kt + 1) * KC + q * 4)
                        : make_float4(0.f, 0.f, 0.f, 0.f);
            }
        }

        // ---- compute chunk kt
        const uint32_t* Au = (const uint32_t*)Asb[buf];
        const uint32_t* Bu = (const uint32_t*)Bsb[buf];
        #pragma unroll
        for (int k8 = 0; k8 < KC / 8; ++k8) {
            const int kc0 = k8 * 8 + tg;
            uint32_t af[3][4];
            #pragma unroll
            for (int am = 0; am < 3; ++am) {
                int row = wm * 48 + am * 16 + g;
                af[am][0] = Au[row * PITCH + kc0];
                af[am][1] = Au[(row + 8) * PITCH + kc0];
                af[am][2] = Au[row * PITCH + kc0 + 4];
                af[am][3] = Au[(row + 8) * PITCH + kc0 + 4];
            }
            uint32_t bf[6][2];
            #pragma unroll
            for (int an = 0; an < 6; ++an) {
                int col = wn * 48 + an * 8 + g;
                bf[an][0] = Bu[col * PITCH + kc0];
                bf[an][1] = Bu[col * PITCH + kc0 + 4];
            }
            #pragma unroll
            for (int am = 0; am < 3; ++am)
                #pragma unroll
                for (int an = 0; an < 6; ++an)
                    mma_tf32(acc[am][an], af[am], bf[an]);
        }
    }
    __syncthreads();

    // ---- epilogue: accumulators -> qkv smem (rows >= 132 dropped)
    #pragma unroll
    for (int am = 0; am < 3; ++am) {
        int row = wm * 48 + am * 16 + g;
        #pragma unroll
        for (int an = 0; an < 6; ++an) {
            int col = wn * 48 + an * 8 + tg * 2;
            if (row < MR)
                *(float2*)&qkv[row * QP + col] = make_float2(acc[am][an][0], acc[am][an][1]);
            if (row + 8 < MR)
                *(float2*)&qkv[(row + 8) * QP + col] = make_float2(acc[am][an][2], acc[am][an][3]);
        }
    }
    __syncthreads();

    // ---- scores (causal) ----
    const float scale = 0.044194173824159216f;   // 512^-0.5
    for (int idx = tid; idx < BPC * TT * TT; idx += NT) {
        int lb  = idx / (TT * TT);
        int rem = idx - lb * TT * TT;
        int t = rem / TT, ss = rem - t * TT;
        if (ss <= t) {
            const float4* qp = (const float4*)&qkv[(lb * TT + t) * QP];
            const float4* kp = (const float4*)&qkv[(lb * TT + ss) * QP + DK];
            float a = 0.f;
            #pragma unroll
            for (int dq = 0; dq < DK / 4; ++dq) {
                float4 qv = qp[dq], kv = kp[dq];
                a += qv.x * kv.x + qv.y * kv.y + qv.z * kv.z + qv.w * kv.w;
            }
            sc[(lb * TT + t) * SP + ss] = a * scale;
        }
    }
    __syncthreads();

    // ---- softmax: thread per row ----
    if (tid < MR) {
        int t = tid % TT;
        float* row = sc + tid * SP;
        float m = row[0];
        for (int ss = 1; ss <= t; ++ss) m = fmaxf(m, row[ss]);
        float sum = 0.f;
        for (int ss = 0; ss <= t; ++ss) {
            float e = __expf(row[ss] - m);
            row[ss] = e;
            sum += e;
        }
        float inv = 1.f / sum;
        for (int ss = 0; ss <= t; ++ss) row[ss] *= inv;
    }
    __syncthreads();

    // ---- PV + coalesced store ----
    for (int idx = tid; idx < BPC * TT * DK; idx += NT) {
        int lb  = idx / (TT * DK);
        int rem = idx - lb * TT * DK;
        int t = rem / DK, d = rem - t * DK;
        size_t b = (size_t)blockIdx.x * BPC + lb;
        if (b < (size_t)Btot) {
            const float* wrow = sc + (lb * TT + t) * SP;
            float a = 0.f;
            for (int ss = 0; ss <= t; ++ss)
                a = fmaf(wrow[ss], qkv[(lb * TT + ss) * QP + 2 * DK + d], a);
            out[b * TT * DK + (size_t)t * DK + d] = a;
        }
    }
}

extern "C" void kernel_launch(void* const* d_in, const int* in_sizes, int n_in,
                              void* d_out, int out_size) {
    const float* x  = (const float*)d_in[0];
    const float* Wq = (const float*)d_in[1];
    const float* Wk = (const float*)d_in[2];
    const float* Wv = (const float*)d_in[3];
    float* out = (float*)d_out;

    int B = in_sizes[0] / (TT * CC);
    size_t Mtot = (size_t)B * TT;
    int grid = (B + BPC - 1) / BPC;
    int smem = SMEM_FLOATS * 4;        // 220320 B

    prep_w<<<(NJ * CC + 255) / 256, 256>>>(Wq, Wk, Wv);
    cudaFuncSetAttribute(head_fused, cudaFuncAttributeMaxDynamicSharedMemorySize, smem);
    head_fused<<<grid, NT, smem>>>(x, out, B, Mtot);
}

// round 5
// speedup vs baseline: 1.8649x; 1.8649x over previous
#include <cuda_runtime.h>
#include <cuda_fp16.h>
#include <cstdint>

#define BB 4096
#define TT 33
#define CC 512
#define DK 64
#define NJ 192           // 3*DK
#define MT 128           // CTA M tile
#define KC 64            // K chunk (halves)
#define NCH (CC / KC)    // 8 chunks
#define PITCH_H 72       // smem row pitch in halves (= 36 u32, conflict-free)
#define NT1 512          // 16 warps: 4m x 4n

__device__ __align__(16) __half g_wh[NJ * CC];        // fp16 W, [n][c]
__device__ float g_qkv[(size_t)BB * TT * NJ];         // qkv rows, [m][n] fp32

__device__ __forceinline__ void mma_f16(float* d, const uint32_t* a, const uint32_t* b) {
    asm volatile(
        "mma.sync.aligned.m16n8k16.row.col.f32.f16.f16.f32 "
        "{%0,%1,%2,%3}, {%4,%5,%6,%7}, {%8,%9}, {%0,%1,%2,%3};\n"
        : "+f"(d[0]), "+f"(d[1]), "+f"(d[2]), "+f"(d[3])
        : "r"(a[0]), "r"(a[1]), "r"(a[2]), "r"(a[3]), "r"(b[0]), "r"(b[1]));
}

__device__ __forceinline__ void cp_async16(void* smem_dst, const void* gsrc) {
    uint32_t s = (uint32_t)__cvta_generic_to_shared(smem_dst);
    asm volatile("cp.async.cg.shared.global [%0], [%1], 16;\n" :: "r"(s), "l"(gsrc));
}
#define CP_COMMIT() asm volatile("cp.async.commit_group;\n" ::: "memory")
#define CP_WAIT0()  asm volatile("cp.async.wait_group 0;\n" ::: "memory")

__device__ __forceinline__ uint32_t pack_h2(float a, float b) {
    __half2 h = __halves2half2(__float2half_rn(a), __float2half_rn(b));
    return *(uint32_t*)&h;
}

// ---------------- prep: W -> fp16, concatenated [192][512] ----------------
__global__ void prep_w(const float* __restrict__ Wq, const float* __restrict__ Wk,
                       const float* __restrict__ Wv) {
    int i4 = blockIdx.x * blockDim.x + threadIdx.x;      // float4 index
    if (i4 < NJ * CC / 4) {
        int i = i4 * 4;
        int n = i / CC, c = i - n * CC;
        const float* src = (n < DK)     ? (Wq + n * CC + c)
                         : (n < 2 * DK) ? (Wk + (n - DK) * CC + c)
                                        : (Wv + (n - 2 * DK) * CC + c);
        float4 v = *(const float4*)src;
        uint32_t lo = pack_h2(v.x, v.y), hi = pack_h2(v.z, v.w);
        *(uint2*)&g_wh[i] = make_uint2(lo, hi);
    }
}

// ---------------- GEMM: g_qkv[m][n] = sum_c x[m][c] * W[n][c] (fp16 MMA) ----------
__global__ __launch_bounds__(NT1, 1)
void qkv_gemm(const float* __restrict__ x, size_t Mtot) {
    extern __shared__ __half smh[];
    __half* Ash[2] = { smh,                     smh + MT * PITCH_H };
    __half* Bsh[2] = { smh + 2 * MT * PITCH_H,  smh + 2 * MT * PITCH_H + NJ * PITCH_H };

    const int tid  = threadIdx.x;
    const int wid  = tid >> 5, lane = tid & 31;
    const int wn   = wid & 3;          // n offset 48*wn
    const int wm   = wid >> 2;         // m offset 32*wm (0..3)
    const int g    = lane >> 2;        // 0..7
    const int tg   = lane & 3;         // 0..3
    const int r0   = tid >> 2;         // 0..127 (A staging row)
    const int seg  = tid & 3;          // 16-float segment within chunk
    const size_t mbase = (size_t)blockIdx.x * MT;

    float acc[2][6][4];
    #pragma unroll
    for (int i = 0; i < 2; ++i)
        #pragma unroll
        for (int j = 0; j < 6; ++j)
            #pragma unroll
            for (int e = 0; e < 4; ++e) acc[i][j][e] = 0.f;

    float4 areg[4];

    // ---- prologue: chunk 0
    for (int idx = tid; idx < NJ * 8; idx += NT1) {      // B chunk 0 (192 x 64 halves)
        int n = idx >> 3, j = idx & 7;
        cp_async16(&Bsh[0][n * PITCH_H + j * 8], g_wh + (size_t)n * CC + j * 8);
    }
    CP_COMMIT();
    {
        size_t m = mbase + (size_t)r0;
        bool ok = (m < Mtot);
        #pragma unroll
        for (int i = 0; i < 4; ++i)
            areg[i] = ok ? *(const float4*)(x + m * CC + seg * 16 + i * 4)
                         : make_float4(0.f, 0.f, 0.f, 0.f);
    }

    for (int kt = 0; kt < NCH; ++kt) {
        const int buf = kt & 1;
        __syncthreads();               // prev compute done; buffers reusable
        {                              // STS A as half2 (8 u32 per thread)
            uint32_t* dst = (uint32_t*)&Ash[buf][r0 * PITCH_H + seg * 16];
            #pragma unroll
            for (int i = 0; i < 4; ++i) {
                dst[i * 2 + 0] = pack_h2(areg[i].x, areg[i].y);
                dst[i * 2 + 1] = pack_h2(areg[i].z, areg[i].w);
            }
        }
        CP_WAIT0();
        __syncthreads();

        if (kt + 1 < NCH) {            // prefetch chunk kt+1
            const int nb = buf ^ 1;
            for (int idx = tid; idx < NJ * 8; idx += NT1) {
                int n = idx >> 3, j = idx & 7;
                cp_async16(&Bsh[nb][n * PITCH_H + j * 8],
                           g_wh + (size_t)n * CC + (kt + 1) * KC + j * 8);
            }
            CP_COMMIT();
            size_t m = mbase + (size_t)r0;
            bool ok = (m < Mtot);
            #pragma unroll
            for (int i = 0; i < 4; ++i)
                areg[i] = ok ? *(const float4*)(x + m * CC + (kt + 1) * KC + seg * 16 + i * 4)
                             : make_float4(0.f, 0.f, 0.f, 0.f);
        }

        // ---- compute chunk kt: 4 k16 steps
        const uint32_t* Au = (const uint32_t*)Ash[buf];  // pitch 36 u32
        const uint32_t* Bu = (const uint32_t*)Bsh[buf];
        #pragma unroll
        for (int k16 = 0; k16 < KC / 16; ++k16) {
            const int kc0 = k16 * 8 + tg;                // u32 (half2) offset
            uint32_t af[2][4];
            #pragma unroll
            for (int am = 0; am < 2; ++am) {
                int row = wm * 32 + am * 16 + g;
                af[am][0] = Au[row * 36 + kc0];
                af[am][1] = Au[(row + 8) * 36 + kc0];
                af[am][2] = Au[row * 36 + kc0 + 4];
                af[am][3] = Au[(row + 8) * 36 + kc0 + 4];
            }
            uint32_t bf[6][2];
            #pragma unroll
            for (int an = 0; an < 6; ++an) {
                int col = wn * 48 + an * 8 + g;
                bf[an][0] = Bu[col * 36 + kc0];
                bf[an][1] = Bu[col * 36 + kc0 + 4];
            }
            #pragma unroll
            for (int am = 0; am < 2; ++am)
                #pragma unroll
                for (int an = 0; an < 6; ++an)
                    mma_f16(acc[am][an], af[am], bf[an]);
        }
    }

    // ---- epilogue: direct STG.64
    #pragma unroll
    for (int am = 0; am < 2; ++am) {
        size_t row = mbase + wm * 32 + am * 16 + g;
        #pragma unroll
        for (int an = 0; an < 6; ++an) {
            int col = wn * 48 + an * 8 + tg * 2;
            if (row < Mtot)
                *(float2*)&g_qkv[row * NJ + col] =
                    make_float2(acc[am][an][0], acc[am][an][1]);
            if (row + 8 < Mtot)
                *(float2*)&g_qkv[(row + 8) * NJ + col] =
                    make_float2(acc[am][an][2], acc[am][an][3]);
        }
    }
}

// ---------------- attention: per-batch causal softmax + PV (R3, proven) ----------
#define QP 196
#define SP 34
__global__ __launch_bounds__(128)
void attn(float* __restrict__ out) {
    __shared__ float qk[TT * QP];
    __shared__ float sc[TT * SP];
    const int b = blockIdx.x, tid = threadIdx.x;
    const float* src = g_qkv + (size_t)b * TT * NJ;

    for (int i4 = tid; i4 < TT * NJ / 4; i4 += 128) {
        int e = i4 * 4;
        int row = e / NJ, col = e - row * NJ;
        *(float4*)&qk[row * QP + col] = *(const float4*)(src + e);
    }
    __syncthreads();

    const float scale = 0.044194173824159216f;   // 512^-0.5
    for (int idx = tid; idx < TT * TT; idx += 128) {
        int t = idx / TT, ss = idx - t * TT;
        if (ss <= t) {
            const float4* qp = (const float4*)&qk[t * QP];
            const float4* kp = (const float4*)&qk[ss * QP + DK];
            float a = 0.f;
            #pragma unroll
            for (int dq = 0; dq < DK / 4; ++dq) {
                float4 qv = qp[dq], kv = kp[dq];
                a += qv.x * kv.x + qv.y * kv.y + qv.z * kv.z + qv.w * kv.w;
            }
            sc[t * SP + ss] = a * scale;
        }
    }
    __syncthreads();

    if (tid < TT) {
        int t = tid;
        float* row = sc + t * SP;
        float m = row[0];
        for (int ss = 1; ss <= t; ++ss) m = fmaxf(m, row[ss]);
        float sum = 0.f;
        for (int ss = 0; ss <= t; ++ss) {
            float e = __expf(row[ss] - m);
            row[ss] = e;
            sum += e;
        }
        float inv = 1.f / sum;
        for (int ss = 0; ss <= t; ++ss) row[ss] *= inv;
    }
    __syncthreads();

    float* ob = out + (size_t)b * TT * DK;
    for (int idx = tid; idx < TT * DK; idx += 128) {
        int t = idx / DK, d = idx - t * DK;
        float a = 0.f;
        for (int ss = 0; ss <= t; ++ss)
            a = fmaf(sc[t * SP + ss], qk[ss * QP + 2 * DK + d], a);
        ob[idx] = a;
    }
}

extern "C" void kernel_launch(void* const* d_in, const int* in_sizes, int n_in,
                              void* d_out, int out_size) {
    const float* x  = (const float*)d_in[0];
    const float* Wq = (const float*)d_in[1];
    const float* Wk = (const float*)d_in[2];
    const float* Wv = (const float*)d_in[3];
    float* out = (float*)d_out;

    int B = in_sizes[0] / (TT * CC);
    size_t Mtot = (size_t)B * TT;
    int gridG = (int)((Mtot + MT - 1) / MT);
    int smemG = (2 * MT * PITCH_H + 2 * NJ * PITCH_H) * 2;   // 92160 B

    prep_w<<<(NJ * CC / 4 + 255) / 256, 256>>>(Wq, Wk, Wv);
    cudaFuncSetAttribute(qkv_gemm, cudaFuncAttributeMaxDynamicSharedMemorySize, smemG);
    qkv_gemm<<<gridG, NT1, smemG>>>(x, Mtot);
    attn<<<B, 128>>>(out);
}

// round 6
// speedup vs baseline: 2.2633x; 1.2136x over previous
#include <cuda_runtime.h>
#include <cuda_fp16.h>
#include <cstdint>

#define BB 4096
#define TT 33
#define CC 512
#define DK 64
#define NJ 192           // 3*DK
#define MT 128           // CTA M tile
#define KC 64            // K chunk (halves)
#define NCH (CC / KC)    // 8 chunks
#define PITCH_H 72       // smem row pitch in halves (144B, conflict-free for LDS+LDSM)
#define ROWB 144         // pitch in bytes
#define NT1 512          // 16 warps: 4m x 4n

// byte offsets inside dynamic smem
#define OFF_A0 0
#define OFF_A1 (MT * ROWB)                  // 18432
#define OFF_B0 (2 * MT * ROWB)              // 36864
#define OFF_B1 (OFF_B0 + NJ * ROWB)         // 64512
#define SMEM_G (OFF_B1 + NJ * ROWB)         // 92160

__device__ __align__(16) __half g_wh[NJ * CC];        // fp16 W, [n][c]
__device__ float g_qkv[(size_t)BB * TT * NJ];         // qkv rows, [m][n] fp32

__device__ __forceinline__ void mma_f16(float* d, const uint32_t* a, const uint32_t* b) {
    asm volatile(
        "mma.sync.aligned.m16n8k16.row.col.f32.f16.f16.f32 "
        "{%0,%1,%2,%3}, {%4,%5,%6,%7}, {%8,%9}, {%0,%1,%2,%3};\n"
        : "+f"(d[0]), "+f"(d[1]), "+f"(d[2]), "+f"(d[3])
        : "r"(a[0]), "r"(a[1]), "r"(a[2]), "r"(a[3]), "r"(b[0]), "r"(b[1]));
}

__device__ __forceinline__ void ldsm_x4(uint32_t& r0, uint32_t& r1, uint32_t& r2,
                                        uint32_t& r3, uint32_t addr) {
    asm volatile("ldmatrix.sync.aligned.m8n8.x4.shared.b16 {%0,%1,%2,%3}, [%4];"
                 : "=r"(r0), "=r"(r1), "=r"(r2), "=r"(r3) : "r"(addr));
}

__device__ __forceinline__ void cp_async16(uint32_t smem_dst, const void* gsrc) {
    asm volatile("cp.async.cg.shared.global [%0], [%1], 16;\n" :: "r"(smem_dst), "l"(gsrc));
}
#define CP_COMMIT() asm volatile("cp.async.commit_group;\n" ::: "memory")
#define CP_WAIT0()  asm volatile("cp.async.wait_group 0;\n" ::: "memory")

__device__ __forceinline__ uint32_t pack_h2(float a, float b) {
    __half2 h = __halves2half2(__float2half_rn(a), __float2half_rn(b));
    return *(uint32_t*)&h;
}

// ---------------- prep: W -> fp16, concatenated [192][512] ----------------
__global__ void prep_w(const float* __restrict__ Wq, const float* __restrict__ Wk,
                       const float* __restrict__ Wv) {
    int i4 = blockIdx.x * blockDim.x + threadIdx.x;
    if (i4 < NJ * CC / 4) {
        int i = i4 * 4;
        int n = i / CC, c = i - n * CC;
        const float* src = (n < DK)     ? (Wq + n * CC + c)
                         : (n < 2 * DK) ? (Wk + (n - DK) * CC + c)
                                        : (Wv + (n - 2 * DK) * CC + c);
        float4 v = *(const float4*)src;
        *(uint2*)&g_wh[i] = make_uint2(pack_h2(v.x, v.y), pack_h2(v.z, v.w));
    }
}

// ---------------- GEMM: g_qkv[m][n] = sum_c x[m][c] * W[n][c] (fp16 MMA) ----------
__global__ __launch_bounds__(NT1, 1)
void qkv_gemm(const float* __restrict__ x, size_t Mtot) {
    extern __shared__ __half smh[];
    const uint32_t sbase = (uint32_t)__cvta_generic_to_shared(smh);

    const int tid  = threadIdx.x;
    const int wid  = tid >> 5, lane = tid & 31;
    const int wn   = wid & 3;          // n offset 48*wn
    const int wm   = wid >> 2;         // m offset 32*wm (0..3)
    const int g    = lane >> 2;
    const int tg   = lane & 3;
    const int r0   = tid >> 2;         // 0..127 A staging row
    const int seg  = tid & 3;          // 16-float segment
    const size_t mbase = (size_t)blockIdx.x * MT;

    // LDSM per-lane byte offsets (within a buffer)
    const uint32_t a_off = (uint32_t)((wm * 32 + (lane & 15)) * ROWB + ((lane >> 4) & 1) * 16);
    const uint32_t b_off = (uint32_t)((wn * 48 + (lane & 7) + ((lane >> 4) & 1) * 8) * ROWB
                                      + ((lane >> 3) & 1) * 16);

    float acc[2][6][4];
    #pragma unroll
    for (int i = 0; i < 2; ++i)
        #pragma unroll
        for (int j = 0; j < 6; ++j)
            #pragma unroll
            for (int e = 0; e < 4; ++e) acc[i][j][e] = 0.f;

    float4 areg[4];

    // ---- prologue: chunk 0
    for (int idx = tid; idx < NJ * 8; idx += NT1) {      // B chunk 0
        int n = idx >> 3, j = idx & 7;
        cp_async16(sbase + OFF_B0 + n * ROWB + j * 16, g_wh + (size_t)n * CC + j * 8);
    }
    CP_COMMIT();
    {
        size_t m = mbase + (size_t)r0;
        bool ok = (m < Mtot);
        #pragma unroll
        for (int i = 0; i < 4; ++i)
            areg[i] = ok ? *(const float4*)(x + m * CC + seg * 16 + i * 4)
                         : make_float4(0.f, 0.f, 0.f, 0.f);
    }

    for (int kt = 0; kt < NCH; ++kt) {
        const int buf = kt & 1;
        const uint32_t aBuf = sbase + (buf ? OFF_A1 : OFF_A0);
        const uint32_t bBuf = sbase + (buf ? OFF_B1 : OFF_B0);
        __syncthreads();
        {   // STS A as half2
            uint32_t* dst = (uint32_t*)(smh + (buf ? OFF_A1 : OFF_A0) / 2
                                        + r0 * PITCH_H + seg * 16);
            #pragma unroll
            for (int i = 0; i < 4; ++i) {
                dst[i * 2 + 0] = pack_h2(areg[i].x, areg[i].y);
                dst[i * 2 + 1] = pack_h2(areg[i].z, areg[i].w);
            }
        }
        CP_WAIT0();
        __syncthreads();

        if (kt + 1 < NCH) {            // prefetch chunk kt+1
            const uint32_t nbB = sbase + ((buf ^ 1) ? OFF_B1 : OFF_B0);
            for (int idx = tid; idx < NJ * 8; idx += NT1) {
                int n = idx >> 3, j = idx & 7;
                cp_async16(nbB + n * ROWB + j * 16,
                           g_wh + (size_t)n * CC + (kt + 1) * KC + j * 8);
            }
            CP_COMMIT();
            size_t m = mbase + (size_t)r0;
            bool ok = (m < Mtot);
            #pragma unroll
            for (int i = 0; i < 4; ++i)
                areg[i] = ok ? *(const float4*)(x + m * CC + (kt + 1) * KC + seg * 16 + i * 4)
                             : make_float4(0.f, 0.f, 0.f, 0.f);
        }

        // ---- compute chunk kt: 4 k16 steps, ldmatrix fragments
        #pragma unroll
        for (int k16 = 0; k16 < KC / 16; ++k16) {
            const uint32_t kb = k16 * 32;
            uint32_t af[2][4], bf[6][2];
            ldsm_x4(af[0][0], af[0][1], af[0][2], af[0][3], aBuf + a_off + kb);
            ldsm_x4(af[1][0], af[1][1], af[1][2], af[1][3], aBuf + a_off + 16 * ROWB + kb);
            #pragma unroll
            for (int p = 0; p < 3; ++p)
                ldsm_x4(bf[2*p][0], bf[2*p][1], bf[2*p+1][0], bf[2*p+1][1],
                        bBuf + b_off + p * 16 * ROWB + kb);
            #pragma unroll
            for (int am = 0; am < 2; ++am)
                #pragma unroll
                for (int an = 0; an < 6; ++an)
                    mma_f16(acc[am][an], af[am], bf[an]);
        }
    }

    // ---- epilogue: direct STG.64
    #pragma unroll
    for (int am = 0; am < 2; ++am) {
        size_t row = mbase + wm * 32 + am * 16 + g;
        #pragma unroll
        for (int an = 0; an < 6; ++an) {
            int col = wn * 48 + an * 8 + tg * 2;
            if (row < Mtot)
                *(float2*)&g_qkv[row * NJ + col] =
                    make_float2(acc[am][an][0], acc[am][an][1]);
            if (row + 8 < Mtot)
                *(float2*)&g_qkv[(row + 8) * NJ + col] =
                    make_float2(acc[am][an][2], acc[am][an][3]);
        }
    }
}

// ---------------- attention: per-batch causal softmax + PV ----------------
#define QP 196
#define SP 34
__global__ __launch_bounds__(128)
void attn(float* __restrict__ out) {
    __shared__ float qk[TT * QP];
    __shared__ float sc[TT * SP];
    const int b = blockIdx.x, tid = threadIdx.x;
    const int warp = tid >> 5, lane = tid & 31;
    const float* src = g_qkv + (size_t)b * TT * NJ;

    for (int i4 = tid; i4 < TT * NJ / 4; i4 += 128) {
        int e = i4 * 4;
        int row = e / NJ, col = e - row * NJ;
        *(float4*)&qk[row * QP + col] = *(const float4*)(src + e);
    }
    __syncthreads();

    const float scale = 0.044194173824159216f;   // 512^-0.5
    for (int idx = tid; idx < TT * TT; idx += 128) {
        int t = idx / TT, ss = idx - t * TT;
        if (ss <= t) {
            const float4* qp = (const float4*)&qk[t * QP];
            const float4* kp = (const float4*)&qk[ss * QP + DK];
            float a = 0.f;
            #pragma unroll
            for (int dq = 0; dq < DK / 4; ++dq) {
                float4 qv = qp[dq], kv = kp[dq];
                a += qv.x * kv.x + qv.y * kv.y + qv.z * kv.z + qv.w * kv.w;
            }
            sc[t * SP + ss] = a * scale;
        }
    }
    __syncthreads();

    // warp-per-row softmax (row t has t+1 <= 33 entries; lane covers ss, ss+32)
    for (int t = warp; t < TT; t += 4) {
        float* row = sc + t * SP;
        float a0 = (lane <= t)      ? row[lane]      : -3.0e38f;
        float a1 = (lane + 32 <= t) ? row[lane + 32] : -3.0e38f;
        float m = fmaxf(a0, a1);
        #pragma unroll
        for (int o = 16; o; o >>= 1) m = fmaxf(m, __shfl_xor_sync(0xffffffffu, m, o));
        float e0 = (lane <= t)      ? __expf(a0 - m) : 0.f;
        float e1 = (lane + 32 <= t) ? __expf(a1 - m) : 0.f;
        float s = e0 + e1;
        #pragma unroll
        for (int o = 16; o; o >>= 1) s += __shfl_xor_sync(0xffffffffu, s, o);
        float inv = 1.f / s;
        if (lane <= t)      row[lane]      = e0 * inv;
        if (lane + 32 <= t) row[lane + 32] = e1 * inv;
    }
    __syncthreads();

    float* ob = out + (size_t)b * TT * DK;
    for (int idx = tid; idx < TT * DK; idx += 128) {
        int t = idx / DK, d = idx - t * DK;
        float a = 0.f;
        for (int ss = 0; ss <= t; ++ss)
            a = fmaf(sc[t * SP + ss], qk[ss * QP + 2 * DK + d], a);
        ob[idx] = a;
    }
}

extern "C" void kernel_launch(void* const* d_in, const int* in_sizes, int n_in,
                              void* d_out, int out_size) {
    const float* x  = (const float*)d_in[0];
    const float* Wq = (const float*)d_in[1];
    const float* Wk = (const float*)d_in[2];
    const float* Wv = (const float*)d_in[3];
    float* out = (float*)d_out;

    int B = in_sizes[0] / (TT * CC);
    size_t Mtot = (size_t)B * TT;
    int gridG = (int)((Mtot + MT - 1) / MT);

    prep_w<<<(NJ * CC / 4 + 255) / 256, 256>>>(Wq, Wk, Wv);
    cudaFuncSetAttribute(qkv_gemm, cudaFuncAttributeMaxDynamicSharedMemorySize, SMEM_G);
    qkv_gemm<<<gridG, NT1, SMEM_G>>>(x, Mtot);
    attn<<<B, 128>>>(out);
}

// round 7
// speedup vs baseline: 2.6597x; 1.1751x over previous
#include <cuda_runtime.h>
#include <cuda_fp16.h>
#include <cstdint>

#define BB 4096
#define TT 33
#define CC 512
#define DK 64
#define NJ 192           // 3*DK
#define MT 128           // CTA M tile
#define KC 64            // K chunk (halves)
#define NCH (CC / KC)    // 8 chunks
#define PITCH_H 72       // smem row pitch in halves (144B)
#define ROWB 144
#define NT1 512          // 16 warps: 4m x 4n

#define OFF_A0 0
#define OFF_A1 (MT * ROWB)
#define OFF_B0 (2 * MT * ROWB)
#define OFF_B1 (OFF_B0 + NJ * ROWB)
#define SMEM_G (OFF_B1 + NJ * ROWB)         // 92160

__device__ __align__(16) __half g_wh[NJ * CC];            // fp16 W, [n][c]
__device__ __align__(16) __half g_qh[(size_t)BB * TT * NJ];  // fp16 qkv, [m][n]

__device__ __forceinline__ void mma_f16(float* d, const uint32_t* a, const uint32_t* b) {
    asm volatile(
        "mma.sync.aligned.m16n8k16.row.col.f32.f16.f16.f32 "
        "{%0,%1,%2,%3}, {%4,%5,%6,%7}, {%8,%9}, {%0,%1,%2,%3};\n"
        : "+f"(d[0]), "+f"(d[1]), "+f"(d[2]), "+f"(d[3])
        : "r"(a[0]), "r"(a[1]), "r"(a[2]), "r"(a[3]), "r"(b[0]), "r"(b[1]));
}

__device__ __forceinline__ void ldsm_x4(uint32_t& r0, uint32_t& r1, uint32_t& r2,
                                        uint32_t& r3, uint32_t addr) {
    asm volatile("ldmatrix.sync.aligned.m8n8.x4.shared.b16 {%0,%1,%2,%3}, [%4];"
                 : "=r"(r0), "=r"(r1), "=r"(r2), "=r"(r3) : "r"(addr));
}

__device__ __forceinline__ void cp_async16(uint32_t smem_dst, const void* gsrc) {
    asm volatile("cp.async.cg.shared.global [%0], [%1], 16;\n" :: "r"(smem_dst), "l"(gsrc));
}
#define CP_COMMIT() asm volatile("cp.async.commit_group;\n" ::: "memory")
#define CP_WAIT0()  asm volatile("cp.async.wait_group 0;\n" ::: "memory")

__device__ __forceinline__ uint32_t pack_h2(float a, float b) {
    __half2 h = __halves2half2(__float2half_rn(a), __float2half_rn(b));
    return *(uint32_t*)&h;
}

// ---------------- prep: W -> fp16, concatenated [192][512] ----------------
__global__ void prep_w(const float* __restrict__ Wq, const float* __restrict__ Wk,
                       const float* __restrict__ Wv) {
    int i4 = blockIdx.x * blockDim.x + threadIdx.x;
    if (i4 < NJ * CC / 4) {
        int i = i4 * 4;
        int n = i / CC, c = i - n * CC;
        const float* src = (n < DK)     ? (Wq + n * CC + c)
                         : (n < 2 * DK) ? (Wk + (n - DK) * CC + c)
                                        : (Wv + (n - 2 * DK) * CC + c);
        float4 v = *(const float4*)src;
        *(uint2*)&g_wh[i] = make_uint2(pack_h2(v.x, v.y), pack_h2(v.z, v.w));
    }
}

// ---------------- GEMM: g_qh[m][n] = sum_c x[m][c] * W[n][c] (fp16 MMA) ----------
__global__ __launch_bounds__(NT1, 1)
void qkv_gemm(const float* __restrict__ x, size_t Mtot) {
    extern __shared__ __half smh[];
    const uint32_t sbase = (uint32_t)__cvta_generic_to_shared(smh);

    const int tid  = threadIdx.x;
    const int wid  = tid >> 5, lane = tid & 31;
    const int wn   = wid & 3;
    const int wm   = wid >> 2;
    const int g    = lane >> 2;
    const int tg   = lane & 3;
    const int r0   = tid >> 2;
    const int seg  = tid & 3;
    const size_t mbase = (size_t)blockIdx.x * MT;

    const uint32_t a_off = (uint32_t)((wm * 32 + (lane & 15)) * ROWB + ((lane >> 4) & 1) * 16);
    const uint32_t b_off = (uint32_t)((wn * 48 + (lane & 7) + ((lane >> 4) & 1) * 8) * ROWB
                                      + ((lane >> 3) & 1) * 16);

    float acc[2][6][4];
    #pragma unroll
    for (int i = 0; i < 2; ++i)
        #pragma unroll
        for (int j = 0; j < 6; ++j)
            #pragma unroll
            for (int e = 0; e < 4; ++e) acc[i][j][e] = 0.f;

    float4 areg[4];

    for (int idx = tid; idx < NJ * 8; idx += NT1) {
        int n = idx >> 3, j = idx & 7;
        cp_async16(sbase + OFF_B0 + n * ROWB + j * 16, g_wh + (size_t)n * CC + j * 8);
    }
    CP_COMMIT();
    {
        size_t m = mbase + (size_t)r0;
        bool ok = (m < Mtot);
        #pragma unroll
        for (int i = 0; i < 4; ++i)
            areg[i] = ok ? *(const float4*)(x + m * CC + seg * 16 + i * 4)
                         : make_float4(0.f, 0.f, 0.f, 0.f);
    }

    for (int kt = 0; kt < NCH; ++kt) {
        const int buf = kt & 1;
        const uint32_t aBuf = sbase + (buf ? OFF_A1 : OFF_A0);
        const uint32_t bBuf = sbase + (buf ? OFF_B1 : OFF_B0);
        __syncthreads();
        {
            uint32_t* dst = (uint32_t*)(smh + (buf ? OFF_A1 : OFF_A0) / 2
                                        + r0 * PITCH_H + seg * 16);
            #pragma unroll
            for (int i = 0; i < 4; ++i) {
                dst[i * 2 + 0] = pack_h2(areg[i].x, areg[i].y);
                dst[i * 2 + 1] = pack_h2(areg[i].z, areg[i].w);
            }
        }
        CP_WAIT0();
        __syncthreads();

        if (kt + 1 < NCH) {
            const uint32_t nbB = sbase + ((buf ^ 1) ? OFF_B1 : OFF_B0);
            for (int idx = tid; idx < NJ * 8; idx += NT1) {
                int n = idx >> 3, j = idx & 7;
                cp_async16(nbB + n * ROWB + j * 16,
                           g_wh + (size_t)n * CC + (kt + 1) * KC + j * 8);
            }
            CP_COMMIT();
            size_t m = mbase + (size_t)r0;
            bool ok = (m < Mtot);
            #pragma unroll
            for (int i = 0; i < 4; ++i)
                areg[i] = ok ? *(const float4*)(x + m * CC + (kt + 1) * KC + seg * 16 + i * 4)
                             : make_float4(0.f, 0.f, 0.f, 0.f);
        }

        #pragma unroll
        for (int k16 = 0; k16 < KC / 16; ++k16) {
            const uint32_t kb = k16 * 32;
            uint32_t af[2][4], bf[6][2];
            ldsm_x4(af[0][0], af[0][1], af[0][2], af[0][3], aBuf + a_off + kb);
            ldsm_x4(af[1][0], af[1][1], af[1][2], af[1][3], aBuf + a_off + 16 * ROWB + kb);
            #pragma unroll
            for (int p = 0; p < 3; ++p)
                ldsm_x4(bf[2*p][0], bf[2*p][1], bf[2*p+1][0], bf[2*p+1][1],
                        bBuf + b_off + p * 16 * ROWB + kb);
            #pragma unroll
            for (int am = 0; am < 2; ++am)
                #pragma unroll
                for (int an = 0; an < 6; ++an)
                    mma_f16(acc[am][an], af[am], bf[an]);
        }
    }

    // ---- epilogue: pack fp16 pairs, STG.32
    #pragma unroll
    for (int am = 0; am < 2; ++am) {
        size_t row = mbase + wm * 32 + am * 16 + g;
        #pragma unroll
        for (int an = 0; an < 6; ++an) {
            int col = wn * 48 + an * 8 + tg * 2;
            if (row < Mtot)
                *(uint32_t*)&g_qh[row * NJ + col] = pack_h2(acc[am][an][0], acc[am][an][1]);
            if (row + 8 < Mtot)
                *(uint32_t*)&g_qh[(row + 8) * NJ + col] = pack_h2(acc[am][an][2], acc[am][an][3]);
        }
    }
}

// ---------------- attention ----------------
#define QP 196
#define SP 34
__global__ __launch_bounds__(256)
void attn(float* __restrict__ out) {
    __shared__ float qk[TT * QP];
    __shared__ float sc[TT * SP];
    const int b = blockIdx.x, tid = threadIdx.x;
    const int warp = tid >> 5, lane = tid & 31;
    const __half* src = g_qh + (size_t)b * TT * NJ;

    // stage fp16 -> fp32 smem (8 halves per thread-iter)
    for (int i8 = tid; i8 < TT * NJ / 8; i8 += 256) {
        int row = i8 / 24, col = (i8 - row * 24) * 8;
        uint4 u = *(const uint4*)(src + (size_t)row * NJ + col);
        float2 f0 = __half22float2(*(__half2*)&u.x);
        float2 f1 = __half22float2(*(__half2*)&u.y);
        float2 f2 = __half22float2(*(__half2*)&u.z);
        float2 f3 = __half22float2(*(__half2*)&u.w);
        float* d = &qk[row * QP + col];
        *(float4*)d       = make_float4(f0.x, f0.y, f1.x, f1.y);
        *(float4*)(d + 4) = make_float4(f2.x, f2.y, f3.x, f3.y);
    }
    __syncthreads();

    // scores + softmax fused: warp-per-row, lane = ss (lane also covers ss+32)
    const float scale = 0.044194173824159216f;   // 512^-0.5
    for (int t = warp; t < TT; t += 8) {
        const float4* qp = (const float4*)&qk[t * QP];   // broadcast across lanes
        float a0 = -3.0e38f, a1 = -3.0e38f;
        if (lane <= t) {
            const float4* kp = (const float4*)&qk[lane * QP + DK];
            float a = 0.f;
            #pragma unroll
            for (int dq = 0; dq < DK / 4; ++dq) {
                float4 qv = qp[dq], kv = kp[dq];
                a += qv.x * kv.x + qv.y * kv.y + qv.z * kv.z + qv.w * kv.w;
            }
            a0 = a * scale;
        }
        if (lane + 32 <= t) {        // only lane 0 at t == 32
            const float4* kp = (const float4*)&qk[(lane + 32) * QP + DK];
            float a = 0.f;
            #pragma unroll
            for (int dq = 0; dq < DK / 4; ++dq) {
                float4 qv = qp[dq], kv = kp[dq];
                a += qv.x * kv.x + qv.y * kv.y + qv.z * kv.z + qv.w * kv.w;
            }
            a1 = a * scale;
        }
        float m = fmaxf(a0, a1);
        #pragma unroll
        for (int o = 16; o; o >>= 1) m = fmaxf(m, __shfl_xor_sync(0xffffffffu, m, o));
        float e0 = (lane <= t)      ? __expf(a0 - m) : 0.f;
        float e1 = (lane + 32 <= t) ? __expf(a1 - m) : 0.f;
        float s = e0 + e1;
        #pragma unroll
        for (int o = 16; o; o >>= 1) s += __shfl_xor_sync(0xffffffffu, s, o);
        float inv = 1.f / s;
        float* row = sc + t * SP;
        if (lane <= t)      row[lane]      = e0 * inv;
        if (lane + 32 <= t) row[lane + 32] = e1 * inv;
    }
    __syncthreads();

    // PV + coalesced store
    float* ob = out + (size_t)b * TT * DK;
    for (int idx = tid; idx < TT * DK; idx += 256) {
        int t = idx / DK, d = idx - t * DK;
        float a = 0.f;
        for (int ss = 0; ss <= t; ++ss)
            a = fmaf(sc[t * SP + ss], qk[ss * QP + 2 * DK + d], a);
        ob[idx] = a;
    }
}

extern "C" void kernel_launch(void* const* d_in, const int* in_sizes, int n_in,
                              void* d_out, int out_size) {
    const float* x  = (const float*)d_in[0];
    const float* Wq = (const float*)d_in[1];
    const float* Wk = (const float*)d_in[2];
    const float* Wv = (const float*)d_in[3];
    float* out = (float*)d_out;

    int B = in_sizes[0] / (TT * CC);
    size_t Mtot = (size_t)B * TT;
    int gridG = (int)((Mtot + MT - 1) / MT);

    prep_w<<<(NJ * CC / 4 + 255) / 256, 256>>>(Wq, Wk, Wv);
    cudaFuncSetAttribute(qkv_gemm, cudaFuncAttributeMaxDynamicSharedMemorySize, SMEM_G);
    qkv_gemm<<<gridG, NT1, SMEM_G>>>(x, Mtot);
    attn<<<B, 256>>>(out);
}